// round 10
// baseline (speedup 1.0000x reference)
#include <cuda_runtime.h>

#define NLAYERS 7
#define EPS_F 1e-5f

// Shapes (fixed by setup_inputs): bsz=8, C=8, QL=KL=128, A=8, cross_range=2
// pw / out: [64, 1024, 1024] f32;  conv_w: [7,8,8,1,3]; conv_b: [7,8]; prelu_a: [7]
//
// One CTA per (b, q). The CTA's 256KB output region is 16 contiguous 16KB
// chunks (8 rows x 4KB per channel). The WHOLE region is zeroed via 16 TMA
// bulk stores (cp.async.bulk G<-S from a 16KB SMEM zero buffer) -- no LSU
// involvement. The 7-layer conv runs register-resident via __shfl_sync.
// After wait_group 0 + barrier, the ~2% nonzero band values are overwritten
// with 2 STG.128 per compute thread. Zero background is exact:
// expm1(0)=0, 0/(sum+eps)=0.

__device__ __forceinline__ void stcs4(float* p, float4 v) {
    asm volatile("st.global.cs.v4.f32 [%0], {%1,%2,%3,%4};"
                 :: "l"(p), "f"(v.x), "f"(v.y), "f"(v.z), "f"(v.w) : "memory");
}
__device__ __forceinline__ void bulk_store(float* gptr, unsigned saddr, unsigned bytes) {
    asm volatile("cp.async.bulk.global.shared::cta.bulk_group [%0], [%1], %2;"
                 :: "l"(gptr), "r"(saddr), "r"(bytes) : "memory");
}

#define ZFLOATS 4096   // 16KB zero buffer

__global__ __launch_bounds__(256, 4)
void sag_tma(const float* __restrict__ pw,
             const float* __restrict__ conv_w,
             const float* __restrict__ conv_b,
             const float* __restrict__ prelu_a,
             float* __restrict__ out)
{
    __shared__ __align__(16) float sZ[ZFLOATS];   // 16KB zeros (TMA source)
    __shared__ float4 sW4[NLAYERS][8][8];         // [l][ci][co] = (k0,k1,k2,_)
    __shared__ float  sB [NLAYERS][8];
    __shared__ float  sA [NLAYERS];
    __shared__ float  sPS[4][8][8];               // partial row sums [pp][hh][co]
    __shared__ float  sInv[8][8];                 // 1/(rowsum+eps)   [hh][co]

    const int tid = threadIdx.x;
    const int b = blockIdx.x >> 7;                // batch
    const int i = blockIdx.x & 127;               // query index
    const size_t base = ((size_t)(b * 8) * 1024 + (size_t)i * 8) * 1024;

    // compute roles: slab = pp*8+hh (8 lanes per slab), co = lane&7
    const int slab = tid >> 3;
    const int co   = tid & 7;
    const int pp   = slab >> 3;
    const int hh   = slab & 7;
    const int doff = (pp < 2) ? (pp - 2) : (pp - 1);   // {-2,-1,1,2}
    const int j    = i + doff;
    const bool pvalid = (j >= 0) && (j < 128);

    // ---- x load issued first (latency hidden by setup) ----
    float4 v0 = make_float4(0.f,0.f,0.f,0.f), v1 = v0;
    if (pvalid) {
        const float* srcx = pw +
            ((size_t)((b * 8 + co) * 1024 + (i * 8 + hh)) * 1024 + (size_t)j * 8);
        v0 = *(const float4*)srcx;
        v1 = *(const float4*)(srcx + 4);
    }

    // ---- init zero buffer + conv params ----
    {
        float4* z4 = (float4*)sZ;
        #pragma unroll
        for (int g = 0; g < ZFLOATS / 4 / 256; g++)      // 4 iterations
            z4[tid + g * 256] = make_float4(0.f, 0.f, 0.f, 0.f);
    }
    for (int t = tid; t < NLAYERS * 64; t += 256) {
        const int l = t >> 6, rem = t & 63, wco = rem >> 3, wci = rem & 7;
        const float* s = conv_w + ((l * 8 + wco) * 8 + wci) * 3;
        sW4[l][wci][wco] = make_float4(s[0], s[1], s[2], 0.f);
    }
    if (tid < NLAYERS * 8) (&sB[0][0])[tid] = conv_b[tid];
    if (tid < NLAYERS)     sA[tid] = prelu_a[tid];
    __syncthreads();

    // ---- 16 TMA bulk stores: zero the whole 256KB region ----
    // chunk t: channel rc = t>>1, half = t&1 -> 16KB contiguous
    if (tid < 16) {
        asm volatile("fence.proxy.async.shared::cta;" ::: "memory");
        const int rc = tid >> 1, half = tid & 1;
        float* g = out + base + (size_t)rc * (1024 * 1024) + half * ZFLOATS;
        bulk_store(g, (unsigned)__cvta_generic_to_shared(sZ), ZFLOATS * 4);
        asm volatile("cp.async.bulk.commit_group;" ::: "memory");
    }

    // ---- register-resident 7-layer residual conv via shuffles ----
    float x[8] = {v0.x, v0.y, v0.z, v0.w, v1.x, v1.y, v1.z, v1.w};
    float c[8];
    #pragma unroll
    for (int w = 0; w < 8; w++) c[w] = x[w];

    const int gbase = (tid & 31) & 24;            // slab group base lane

    #pragma unroll 1
    for (int l = 0; l < NLAYERS; l++) {
        const float bias = sB[l][co];
        float acc[8];
        #pragma unroll
        for (int w = 0; w < 8; w++) acc[w] = bias;

        #pragma unroll
        for (int ci = 0; ci < 8; ci++) {
            const float4 wv = sW4[l][ci][co];
            const int src = gbase | ci;
            const float r0 = __shfl_sync(0xffffffffu, c[0], src);
            const float r1 = __shfl_sync(0xffffffffu, c[1], src);
            const float r2 = __shfl_sync(0xffffffffu, c[2], src);
            const float r3 = __shfl_sync(0xffffffffu, c[3], src);
            const float r4 = __shfl_sync(0xffffffffu, c[4], src);
            const float r5 = __shfl_sync(0xffffffffu, c[5], src);
            const float r6 = __shfl_sync(0xffffffffu, c[6], src);
            const float r7 = __shfl_sync(0xffffffffu, c[7], src);
            acc[0] += wv.y * r0 + wv.z * r1;
            acc[1] += wv.x * r0 + wv.y * r1 + wv.z * r2;
            acc[2] += wv.x * r1 + wv.y * r2 + wv.z * r3;
            acc[3] += wv.x * r2 + wv.y * r3 + wv.z * r4;
            acc[4] += wv.x * r3 + wv.y * r4 + wv.z * r5;
            acc[5] += wv.x * r4 + wv.y * r5 + wv.z * r6;
            acc[6] += wv.x * r5 + wv.y * r6 + wv.z * r7;
            acc[7] += wv.x * r6 + wv.y * r7;
        }

        const float pa = sA[l];
        #pragma unroll
        for (int w = 0; w < 8; w++) {
            const float y = (acc[w] >= 0.f) ? acc[w] : pa * acc[w];
            c[w] = y + c[w];                      // residual, in place
        }
    }

    // ---- we = expm1(relu(x - sigmoid(conv)) * (1-eye)) ----
    float we[8];
    float partial = 0.f;
    #pragma unroll
    for (int w = 0; w < 8; w++) {
        const float sg = 1.f / (1.f + __expf(-c[w]));
        float sp = fmaxf(x[w] - sg, 0.f);
        if (hh == w) sp = 0.f;                    // self mask
        float v = expm1f(sp);
        if (!pvalid) v = 0.f;
        we[w] = v;
        partial += v;
    }
    sPS[pp][hh][co] = partial;
    __syncthreads();

    if (tid < 64) {
        const int th = tid >> 3, tc = tid & 7;
        const float s = sPS[0][th][tc] + sPS[1][th][tc] + sPS[2][th][tc] + sPS[3][th][tc];
        sInv[th][tc] = 1.f / (s + EPS_F);
    }

    // ---- drain TMA zeros, then overwrite band ----
    if (tid < 16)
        asm volatile("cp.async.bulk.wait_group 0;" ::: "memory");
    __syncthreads();   // orders bulk-complete + sInv for everyone

    if (pvalid) {
        const float inv = sInv[hh][co];
        float* dst = out +
            ((size_t)((b * 8 + co) * 1024 + (i * 8 + hh)) * 1024 + (size_t)j * 8);
        stcs4(dst,     make_float4(we[0]*inv, we[1]*inv, we[2]*inv, we[3]*inv));
        stcs4(dst + 4, make_float4(we[4]*inv, we[5]*inv, we[6]*inv, we[7]*inv));
    }
}

extern "C" void kernel_launch(void* const* d_in, const int* in_sizes, int n_in,
                              void* d_out, int out_size) {
    const float* pw = (const float*)d_in[0];
    const float* cw = (const float*)d_in[1];
    const float* cb = (const float*)d_in[2];
    const float* pa = (const float*)d_in[3];
    sag_tma<<<1024, 256>>>(pw, cw, cb, pa, (float*)d_out);
}